// round 6
// baseline (speedup 1.0000x reference)
#include <cuda_runtime.h>
#include <cstdint>

// ---------------------------------------------------------------------------
// GRU (H=1, single step) over N = B*A = 1,048,576 rows of C=64 floats.
//   x = row[1:64], h0 = row[0]
//   gi = x @ W_ih^T + b_ih ; gh = h0 * W_hh + b_hh
//   r = sig(gi_r+gh_r); z = sig(gi_z+gh_z); n = tanh(gi_n + r*gh_n)
//   h1 = (1-z)*n + z*h0 ; out = h1*w_lin + b_lin
//
// PERSISTENT single-wave kernel: 888 CTAs (148 SMs x 6 resident), each
// grid-strides over 128-row tiles.
//   Per tile: cp.async.cg stream in TWO commit groups (rows 0..63 / 64..127)
//   so the first half computes under wait_group 1 while group B lands.
//   Rows padded to 17 float4 -> conflict-free quarter-warp LDS.128.
//   One thread per row, 3 independent 63-FMA chains, no shuffles.
//   Weights repacked ONCE per CTA (hidden under first tile's DMA).
// Channel-0 weight forced to 0 so h0 rides the same vector load.
// ---------------------------------------------------------------------------

static __device__ __forceinline__ float sigmoidf_fast(float x) {
    return 1.0f / (1.0f + __expf(-x));
}

static __device__ __forceinline__ uint32_t smem_u32(const void* p) {
    return (uint32_t)__cvta_generic_to_shared(p);
}

static __device__ __forceinline__ void cp_async16(uint32_t dst, const void* src) {
    asm volatile("cp.async.cg.shared.global [%0], [%1], 16;"
                 :: "r"(dst), "l"(src) : "memory");
}

#define TPB        128           // threads per block == rows per tile
#define F4_PER_ROW 16            // 64 floats
#define ROW_PAD    17            // padded row stride in float4 (bank-conflict-free)
#define NSM        148
#define CTAS_PER_SM 6

__global__ __launch_bounds__(TPB) void gru_main_kernel(
    const float* __restrict__ in,
    const float* __restrict__ W_ih,   // [3][63] row-major
    const float* __restrict__ W_hh,   // [3]
    const float* __restrict__ b_ih,   // [3]
    const float* __restrict__ b_hh,   // [3]
    const float* __restrict__ w_lin,  // [1]
    const float* __restrict__ b_lin,  // [1]
    float* __restrict__ out,
    int ntiles) {
    __shared__ float4 s_rows[TPB * ROW_PAD];     // 34,816 B
    __shared__ float4 s_wr[16], s_wz[16], s_wn[16];
    __shared__ float  s_sc[9];

    const int tid   = threadIdx.x;
    uint32_t  sbase = smem_u32(s_rows);

    // ---- Once per CTA: queue FIRST tile's DMA, then repack weights under it.
    int tile = blockIdx.x;
    {
        const float4* gp = reinterpret_cast<const float4*>(in)
                         + (size_t)tile * TPB * F4_PER_ROW;
        #pragma unroll
        for (int k = 0; k < 8; k++) {            // group A -> rows 0..63
            int f = k * TPB + tid;
            cp_async16(sbase + (uint32_t)((f >> 4) * ROW_PAD + (f & 15)) * 16u,
                       gp + f);
        }
        asm volatile("cp.async.commit_group;" ::: "memory");
        #pragma unroll
        for (int k = 8; k < 16; k++) {           // group B -> rows 64..127
            int f = k * TPB + tid;
            cp_async16(sbase + (uint32_t)((f >> 4) * ROW_PAD + (f & 15)) * 16u,
                       gp + f);
        }
        asm volatile("cp.async.commit_group;" ::: "memory");
    }

    if (tid < 16) {          // channel c = 4*tid+k; c==0 -> weight 0
        float4 wr, wz, wn;
        float* pr = (float*)&wr; float* pz = (float*)&wz; float* pn = (float*)&wn;
        #pragma unroll
        for (int k = 0; k < 4; k++) {
            int c = 4 * tid + k;
            if (c == 0) { pr[k] = 0.f; pz[k] = 0.f; pn[k] = 0.f; }
            else {
                pr[k] = __ldg(&W_ih[0 * 63 + (c - 1)]);
                pz[k] = __ldg(&W_ih[1 * 63 + (c - 1)]);
                pn[k] = __ldg(&W_ih[2 * 63 + (c - 1)]);
            }
        }
        s_wr[tid] = wr; s_wz[tid] = wz; s_wn[tid] = wn;
    } else if (tid == 16) {
        s_sc[0] = __ldg(&W_hh[0]);
        s_sc[1] = __ldg(&W_hh[1]);
        s_sc[2] = __ldg(&W_hh[2]);
        s_sc[3] = __ldg(&b_ih[0]) + __ldg(&b_hh[0]);   // r bias sum
        s_sc[4] = __ldg(&b_ih[1]) + __ldg(&b_hh[1]);   // z bias sum
        s_sc[5] = __ldg(&b_ih[2]);                     // n: gi bias
        s_sc[6] = __ldg(&b_hh[2]);                     // n: gh bias (inside r*)
        s_sc[7] = __ldg(&w_lin[0]);
        s_sc[8] = __ldg(&b_lin[0]);
    }

    const float4* myrow = s_rows + tid * ROW_PAD;

    // ---- Persistent loop over tiles ----
    for (; tile < ntiles; tile += gridDim.x) {
        // First half: rows 0..63 compute while group B is in flight.
        asm volatile("cp.async.wait_group 1;" ::: "memory");
        __syncthreads();     // publishes group-A copies (+ weights, iter 0)

        if (tid < 64) {
            float4 v0 = myrow[0];
            float  h0 = v0.x;                    // channel 0 (weight forced 0)
            float4 w;
            w = s_wr[0]; float ar = v0.x*w.x + v0.y*w.y + v0.z*w.z + v0.w*w.w;
            w = s_wz[0]; float az = v0.x*w.x + v0.y*w.y + v0.z*w.z + v0.w*w.w;
            w = s_wn[0]; float an = v0.x*w.x + v0.y*w.y + v0.z*w.z + v0.w*w.w;
            #pragma unroll
            for (int j = 1; j < F4_PER_ROW; j++) {
                float4 v = myrow[j];
                w = s_wr[j]; ar += v.x*w.x + v.y*w.y + v.z*w.z + v.w*w.w;
                w = s_wz[j]; az += v.x*w.x + v.y*w.y + v.z*w.z + v.w*w.w;
                w = s_wn[j]; an += v.x*w.x + v.y*w.y + v.z*w.z + v.w*w.w;
            }
            float r  = sigmoidf_fast(ar + h0 * s_sc[0] + s_sc[3]);
            float z  = sigmoidf_fast(az + h0 * s_sc[1] + s_sc[4]);
            float n  = tanhf(an + s_sc[5] + r * (h0 * s_sc[2] + s_sc[6]));
            float h1 = (1.0f - z) * n + z * h0;
            out[(size_t)tile * TPB + tid] = h1 * s_sc[7] + s_sc[8];
        }

        // Second half: rows 64..127.
        asm volatile("cp.async.wait_group 0;" ::: "memory");
        __syncthreads();     // publishes group-B copies

        if (tid >= 64) {
            float4 v0 = myrow[0];
            float  h0 = v0.x;
            float4 w;
            w = s_wr[0]; float ar = v0.x*w.x + v0.y*w.y + v0.z*w.z + v0.w*w.w;
            w = s_wz[0]; float az = v0.x*w.x + v0.y*w.y + v0.z*w.z + v0.w*w.w;
            w = s_wn[0]; float an = v0.x*w.x + v0.y*w.y + v0.z*w.z + v0.w*w.w;
            #pragma unroll
            for (int j = 1; j < F4_PER_ROW; j++) {
                float4 v = myrow[j];
                w = s_wr[j]; ar += v.x*w.x + v.y*w.y + v.z*w.z + v.w*w.w;
                w = s_wz[j]; az += v.x*w.x + v.y*w.y + v.z*w.z + v.w*w.w;
                w = s_wn[j]; an += v.x*w.x + v.y*w.y + v.z*w.z + v.w*w.w;
            }
            float r  = sigmoidf_fast(ar + h0 * s_sc[0] + s_sc[3]);
            float z  = sigmoidf_fast(az + h0 * s_sc[1] + s_sc[4]);
            float n  = tanhf(an + s_sc[5] + r * (h0 * s_sc[2] + s_sc[6]));
            float h1 = (1.0f - z) * n + z * h0;
            out[(size_t)tile * TPB + tid] = h1 * s_sc[7] + s_sc[8];
        }

        // All reads of s_rows done -> safe to overwrite with next tile's DMA.
        __syncthreads();

        int next = tile + gridDim.x;
        if (next < ntiles) {
            const float4* gp = reinterpret_cast<const float4*>(in)
                             + (size_t)next * TPB * F4_PER_ROW;
            #pragma unroll
            for (int k = 0; k < 8; k++) {
                int f = k * TPB + tid;
                cp_async16(sbase + (uint32_t)((f >> 4) * ROW_PAD + (f & 15)) * 16u,
                           gp + f);
            }
            asm volatile("cp.async.commit_group;" ::: "memory");
            #pragma unroll
            for (int k = 8; k < 16; k++) {
                int f = k * TPB + tid;
                cp_async16(sbase + (uint32_t)((f >> 4) * ROW_PAD + (f & 15)) * 16u,
                           gp + f);
            }
            asm volatile("cp.async.commit_group;" ::: "memory");
        } else {
            // Keep group-accounting consistent for the final loop iteration.
            asm volatile("cp.async.commit_group;" ::: "memory");
            asm volatile("cp.async.commit_group;" ::: "memory");
        }
    }
}

extern "C" void kernel_launch(void* const* d_in, const int* in_sizes, int n_in,
                              void* d_out, int out_size) {
    const float* inputs = (const float*)d_in[0];
    const float* W_ih   = (const float*)d_in[1];
    const float* W_hh   = (const float*)d_in[2];
    const float* b_ih   = (const float*)d_in[3];
    const float* b_hh   = (const float*)d_in[4];
    const float* w_lin  = (const float*)d_in[5];
    const float* b_lin  = (const float*)d_in[6];
    float* out = (float*)d_out;

    int nrows  = in_sizes[0] / 64;               // B*A = 1,048,576
    int ntiles = nrows / TPB;                    // 8192 (exact)

    int blocks = NSM * CTAS_PER_SM;              // 888: single wave at occ 6
    if (blocks > ntiles) blocks = ntiles;

    gru_main_kernel<<<blocks, TPB>>>(inputs, W_ih, W_hh, b_ih, b_hh,
                                     w_lin, b_lin, out, ntiles);
}